// round 16
// baseline (speedup 1.0000x reference)
#include <cuda_runtime.h>
#include <cuda_fp16.h>
#include <cstdint>

// ---------------- problem constants ----------------
#define MROWS   8192
#define NFULL   4096
#define KACT    1024
#define NACT    1024

#define BM      128
#define BN      64
#define BKB     64                        // fp16 k-elements per stage chunk (128B/row)
#define NITER   (KACT / BKB)              // 16
#define STAGES  3
#define A_PLANE (128 * 128)               // 16384 B (x fp16)
#define B_PLANE (64 * 128)                // 8192 B (w fp16)
#define STAGE_BYTES (A_PLANE + B_PLANE)           // 24576
#define SMEM_BYTES  (STAGES * STAGE_BYTES + 128)  // 73856; epilogue tile 32KB fits
#define NTHREADS 256

#define WSCALE     2048.0f
#define INV_WSCALE (1.0f / 2048.0f)

// scratch: gathered fp16 activations, fp16 weights (x WSCALE), inverse maps
__device__ __half g_xa[(size_t)MROWS * KACT];
__device__ __half g_wf[(size_t)NACT * KACT];
__device__ int    g_pos[NFULL];    // column -> position in in_idx  (-1 inactive)
__device__ int    g_opos[NFULL];   // column -> position in out_idx (-1 inactive)

// ---------------- helpers ----------------
__device__ __forceinline__ uint32_t smem_u32(const void* p) {
    uint32_t a;
    asm("{ .reg .u64 t; cvta.to.shared.u64 t, %1; cvt.u32.u64 %0, t; }" : "=r"(a) : "l"(p));
    return a;
}
__device__ __forceinline__ void cp_async16(uint32_t dst, const void* src) {
    asm volatile("cp.async.cg.shared.global [%0], [%1], 16;" :: "r"(dst), "l"(src));
}
__device__ __forceinline__ void ldsm4(uint32_t* r, uint32_t addr) {
    asm volatile("ldmatrix.sync.aligned.m8n8.x4.shared.b16 {%0,%1,%2,%3}, [%4];"
                 : "=r"(r[0]), "=r"(r[1]), "=r"(r[2]), "=r"(r[3]) : "r"(addr));
}
__device__ __forceinline__ void mma_f16(float* d, const uint32_t* a,
                                        uint32_t b0, uint32_t b1) {
    asm volatile(
        "mma.sync.aligned.m16n8k16.row.col.f32.f16.f16.f32 "
        "{%0,%1,%2,%3}, {%4,%5,%6,%7}, {%8,%9}, {%0,%1,%2,%3};"
        : "+f"(d[0]), "+f"(d[1]), "+f"(d[2]), "+f"(d[3])
        : "r"(a[0]), "r"(a[1]), "r"(a[2]), "r"(a[3]), "r"(b0), "r"(b1));
}
__device__ __forceinline__ uint32_t pack_h2(float a, float b) {
    __half2 t = __floats2half2_rn(a, b);
    return *reinterpret_cast<uint32_t*>(&t);
}
// swizzled 16B-chunk offset within a 128B-row plane (8 chunks/row)
__device__ __forceinline__ uint32_t swz(int r, int p) {
    return (uint32_t)(r * 128 + (((p + (r >> 1)) & 7) << 4));
}
__device__ __forceinline__ int bsearch_idx(const int* __restrict__ idx, int c) {
    int lo = 0, hi = KACT - 1, found = -1;
    while (lo <= hi) {
        int mid = (lo + hi) >> 1;
        int v = __ldg(idx + mid);
        if (v == c) { found = mid; break; }
        if (v < c) lo = mid + 1; else hi = mid - 1;
    }
    return found;
}

// ---------------- kernel 1: inverse column maps ----------------
__global__ void build_maps_kernel(const int* __restrict__ in_idx,
                                  const int* __restrict__ out_idx) {
    int c = blockIdx.x * blockDim.x + threadIdx.x;
    if (c >= NFULL) return;
    g_pos[c]  = bsearch_idx(in_idx, c);
    g_opos[c] = bsearch_idx(out_idx, c);
}

// ---------------- kernel 2: gather x[:, in_idx] -> fp16, coalesced writes ----------------
__global__ __launch_bounds__(256) void gather_kernel(const float* __restrict__ x) {
    __shared__ int    s_pos[NFULL];          // 16 KB
    __shared__ __half s_stage[4 * KACT];     // 8 KB
    const int tid = threadIdx.x;
    for (int i = tid; i < NFULL; i += 256) s_pos[i] = g_pos[i];
    __syncthreads();

    const size_t r0 = (size_t)blockIdx.x * 4;
    const float4* __restrict__ x4 = (const float4*)x;
    #pragma unroll
    for (int i = 0; i < 16; i++) {
        int f = tid + i * 256;
        int rowl = f >> 10;
        int c4 = f & 1023;
        float4 v = x4[(r0 + rowl) * (NFULL / 4) + c4];
        int c = c4 * 4;
        float vv[4] = {v.x, v.y, v.z, v.w};
        #pragma unroll
        for (int j = 0; j < 4; j++) {
            int p = s_pos[c + j];
            if (p >= 0) s_stage[rowl * KACT + p] = __float2half_rn(vv[j]);
        }
    }
    __syncthreads();

    // write 4 rows x 1024 fp16 = 512 uint4, fully coalesced
    uint4* __restrict__ dst = (uint4*)(g_xa + r0 * KACT);
    const uint4* __restrict__ src = (const uint4*)s_stage;
    dst[tid]       = src[tid];
    dst[tid + 256] = src[tid + 256];
}

// ---------------- kernel 3: W*2048 -> fp16 ----------------
__global__ __launch_bounds__(256) void conv_w_kernel(const float* __restrict__ W) {
    int i = blockIdx.x * blockDim.x + threadIdx.x;      // float4 index
    float4 v = ((const float4*)W)[i];
    uint2 hp;
    hp.x = pack_h2(v.x * WSCALE, v.y * WSCALE);
    hp.y = pack_h2(v.z * WSCALE, v.w * WSCALE);
    ((uint2*)g_wf)[i] = hp;
}

// ---------------- kernel 4: fp16 mma GEMM + fused zero-fill/bias/scatter ----------------
extern __shared__ char dynsmem[];

__global__ __launch_bounds__(NTHREADS, 3)
void nsl_mma_gemm(const float* __restrict__ bias, const int* __restrict__ out_idx,
                  float* __restrict__ out) {
    __shared__ float s_bias[BN];

    const int tid  = threadIdx.x;
    const int wid  = tid >> 5;
    const int lane = tid & 31;
    const int wm   = wid & 3;         // 0..3 : 32-row band
    const int wn   = wid >> 2;        // 0..1 : 32-col band
    const int m0   = blockIdx.y * BM;
    const int n0   = blockIdx.x * BN; // local col block in [0, 1024)

    if (tid < BN) s_bias[tid] = __ldg(bias + n0 + tid);

    const uint32_t sbase = (smem_u32(dynsmem) + 127) & ~127u;

    // per-thread load assignment: 128B rows, 8 segs/row
    // A: 128 rows x 8 segs = 1024 -> 4/thread; B: 64 rows x 8 segs = 512 -> 2/thread
    const int r = tid >> 3, p = tid & 7;        // r 0..31, p 0..7
    const __half* __restrict__ srcA = g_xa + (size_t)m0 * KACT + (size_t)r * KACT + p * 8;
    const __half* __restrict__ srcB = g_wf + (size_t)n0 * KACT + (size_t)r * KACT + p * 8;
    uint32_t dswA[4], dswB[2];
    #pragma unroll
    for (int i = 0; i < 4; i++) dswA[i] = swz(r + i * 32, p);
    #pragma unroll
    for (int i = 0; i < 2; i++) dswB[i] = A_PLANE + swz(r + i * 32, p);

    auto load_stage = [&](int stage, int kc) {
        const uint32_t sb = sbase + stage * STAGE_BYTES;
        const int ko = kc * BKB;
        #pragma unroll
        for (int i = 0; i < 4; i++)
            cp_async16(sb + dswA[i], srcA + (size_t)(i * 32) * KACT + ko);
        #pragma unroll
        for (int i = 0; i < 2; i++)
            cp_async16(sb + dswB[i], srcB + (size_t)(i * 32) * KACT + ko);
        asm volatile("cp.async.commit_group;");
    };

    // ldmatrix per-lane state
    const int lrow = lane & 15;
    const int hi   = lane >> 4;                 // 16B half within k16 step
    const int rot  = (lrow >> 1) & 7;
    uint32_t aRow[2], bRow[2];
    #pragma unroll
    for (int f = 0; f < 2; f++)
        aRow[f] = (uint32_t)((wm * 32 + f * 16 + lrow) * 128);
    #pragma unroll
    for (int q = 0; q < 2; q++)
        bRow[q] = (uint32_t)(A_PLANE + (wn * 32 + q * 16 + lrow) * 128);

    float acc[2][4][4];
    #pragma unroll
    for (int i = 0; i < 2; i++)
        #pragma unroll
        for (int j = 0; j < 4; j++)
            #pragma unroll
            for (int q = 0; q < 4; q++) acc[i][j][q] = 0.f;

    load_stage(0, 0);
    load_stage(1, 1);

    for (int t = 0; t < NITER; t++) {
        if (t < NITER - 1) asm volatile("cp.async.wait_group 1;" ::: "memory");
        else               asm volatile("cp.async.wait_group 0;" ::: "memory");
        __syncthreads();
        if (t + 2 < NITER) load_stage((t + 2) % STAGES, t + 2);

        const uint32_t sb = sbase + (t % STAGES) * STAGE_BYTES;
        #pragma unroll
        for (int kk = 0; kk < 4; kk++) {            // 4 x k16 steps
            const uint32_t co = (uint32_t)(((kk * 2 + hi + rot) & 7) << 4);
            uint32_t a[2][4], bf[2][4];
            ldsm4(a[0],  sb + aRow[0] + co);
            ldsm4(a[1],  sb + aRow[1] + co);
            ldsm4(bf[0], sb + bRow[0] + co);
            ldsm4(bf[1], sb + bRow[1] + co);

            #pragma unroll
            for (int mi = 0; mi < 2; mi++)
                #pragma unroll
                for (int q = 0; q < 2; q++) {
                    mma_f16(acc[mi][2 * q + 0], a[mi], bf[q][0], bf[q][2]);
                    mma_f16(acc[mi][2 * q + 1], a[mi], bf[q][1], bf[q][3]);
                }
        }
    }

    // ---- epilogue: stage tile to smem, then ranged full-width write ----
    __syncthreads();                         // all LDSM reads of pipeline smem done
    float* stile = (float*)dynsmem;          // reuse pipeline smem: 128x64 fp32 = 32 KB

    const int rq = lane >> 2, cq = (lane & 3) * 2;
    #pragma unroll
    for (int mi = 0; mi < 2; mi++) {
        const int rb = wm * 32 + mi * 16 + rq;
        #pragma unroll
        for (int nf = 0; nf < 4; nf++) {
            const int nl = wn * 32 + nf * 8 + cq;
            const float* c = acc[mi][nf];
            stile[rb * BN + nl]           = c[0];
            stile[rb * BN + nl + 1]       = c[1];
            stile[(rb + 8) * BN + nl]     = c[2];
            stile[(rb + 8) * BN + nl + 1] = c[3];
        }
    }
    __syncthreads();

    // owned output-column range (out_idx sorted): [sBeg, sEnd)
    const int j = blockIdx.x;
    const int sBeg = (j == 0)             ? 0     : __ldg(out_idx + n0);
    const int sEnd = (j == NACT / BN - 1) ? NFULL : __ldg(out_idx + n0 + BN);

    for (int c = sBeg + tid; c < sEnd; c += NTHREADS) {
        const int pp  = __ldg(g_opos + c);           // >=0 iff active; then in [n0,n0+64)
        const bool act = (pp >= 0);
        const int nl  = act ? (pp - n0) : 0;
        const float bv = act ? s_bias[nl] : 0.f;
        float* __restrict__ ocol = out + (size_t)m0 * NFULL + c;
        #pragma unroll 8
        for (int m = 0; m < BM; m++) {
            float v = act ? fmaf(stile[m * BN + nl], INV_WSCALE, bv) : 0.f;
            ocol[(size_t)m * NFULL] = v;
        }
    }
}

// ---------------- launch ----------------
extern "C" void kernel_launch(void* const* d_in, const int* in_sizes, int n_in,
                              void* d_out, int out_size) {
    const float* x       = (const float*)d_in[0];
    const float* W       = (const float*)d_in[1];
    const float* b       = (const float*)d_in[2];
    const int*   in_idx  = (const int*)d_in[3];
    const int*   out_idx = (const int*)d_in[4];
    float*       out     = (float*)d_out;

    static bool attr_set = false;
    if (!attr_set) {
        cudaFuncSetAttribute(nsl_mma_gemm, cudaFuncAttributeMaxDynamicSharedMemorySize,
                             SMEM_BYTES);
        attr_set = true;
    }

    build_maps_kernel<<<(NFULL + 255) / 256, 256>>>(in_idx, out_idx);
    conv_w_kernel<<<(NACT * KACT / 4) / 256, 256>>>(W);
    gather_kernel<<<MROWS / 4, 256>>>(x);

    dim3 grid(NACT / BN, MROWS / BM);   // (16, 64) = 1024 CTAs
    nsl_mma_gemm<<<grid, NTHREADS, SMEM_BYTES>>>(b, out_idx, out);
}

// round 17
// speedup vs baseline: 1.1599x; 1.1599x over previous
#include <cuda_runtime.h>
#include <cuda_fp16.h>
#include <cstdint>

// ---------------- problem constants ----------------
#define MROWS   8192
#define NFULL   4096
#define KACT    1024
#define NACT    1024

#define BM      128
#define BN      64
#define BKB     64                        // fp16 k-elements per stage chunk (128B/row)
#define NITER   (KACT / BKB)              // 16
#define STAGES  3
#define A_PLANE (128 * 128)               // 16384 B (x fp16)
#define B_PLANE (64 * 128)                // 8192 B (w fp16)
#define STAGE_BYTES (A_PLANE + B_PLANE)           // 24576
#define SMEM_BYTES  (STAGES * STAGE_BYTES + 128)  // 73856; epilogue tile 32KB fits
#define NTHREADS 256

#define WSCALE     2048.0f
#define INV_WSCALE (1.0f / 2048.0f)

// scratch: gathered fp16 activations, fp16 weights (x WSCALE), inverse maps
__device__ __half g_xa[(size_t)MROWS * KACT];
__device__ __half g_wf[(size_t)NACT * KACT];
__device__ int    g_pos[NFULL];    // column -> position in in_idx  (-1 inactive)
__device__ int    g_opos[NFULL];   // column -> position in out_idx (-1 inactive)

// ---------------- helpers ----------------
__device__ __forceinline__ uint32_t smem_u32(const void* p) {
    uint32_t a;
    asm("{ .reg .u64 t; cvta.to.shared.u64 t, %1; cvt.u32.u64 %0, t; }" : "=r"(a) : "l"(p));
    return a;
}
__device__ __forceinline__ void cp_async16(uint32_t dst, const void* src) {
    asm volatile("cp.async.cg.shared.global [%0], [%1], 16;" :: "r"(dst), "l"(src));
}
__device__ __forceinline__ void ldsm4(uint32_t* r, uint32_t addr) {
    asm volatile("ldmatrix.sync.aligned.m8n8.x4.shared.b16 {%0,%1,%2,%3}, [%4];"
                 : "=r"(r[0]), "=r"(r[1]), "=r"(r[2]), "=r"(r[3]) : "r"(addr));
}
__device__ __forceinline__ void mma_f16(float* d, const uint32_t* a,
                                        uint32_t b0, uint32_t b1) {
    asm volatile(
        "mma.sync.aligned.m16n8k16.row.col.f32.f16.f16.f32 "
        "{%0,%1,%2,%3}, {%4,%5,%6,%7}, {%8,%9}, {%0,%1,%2,%3};"
        : "+f"(d[0]), "+f"(d[1]), "+f"(d[2]), "+f"(d[3])
        : "r"(a[0]), "r"(a[1]), "r"(a[2]), "r"(a[3]), "r"(b0), "r"(b1));
}
__device__ __forceinline__ uint32_t pack_h2(float a, float b) {
    __half2 t = __floats2half2_rn(a, b);
    return *reinterpret_cast<uint32_t*>(&t);
}
// XOR swizzle: 16B-chunk offset within a 128B-row plane (8 chunks/row)
// conflict-free: 8 consecutive rows -> 8 distinct bank-groups for any fixed p
__device__ __forceinline__ uint32_t swz(int r, int p) {
    return (uint32_t)(r * 128 + ((p ^ (r & 7)) << 4));
}
__device__ __forceinline__ int bsearch_idx(const int* __restrict__ idx, int c) {
    int lo = 0, hi = KACT - 1, found = -1;
    while (lo <= hi) {
        int mid = (lo + hi) >> 1;
        int v = __ldg(idx + mid);
        if (v == c) { found = mid; break; }
        if (v < c) lo = mid + 1; else hi = mid - 1;
    }
    return found;
}

// ---------------- kernel 1: inverse column maps ----------------
__global__ void build_maps_kernel(const int* __restrict__ in_idx,
                                  const int* __restrict__ out_idx) {
    int c = blockIdx.x * blockDim.x + threadIdx.x;
    if (c >= NFULL) return;
    g_pos[c]  = bsearch_idx(in_idx, c);
    g_opos[c] = bsearch_idx(out_idx, c);
}

// ---------------- kernel 2: gather x[:, in_idx] -> fp16, coalesced writes ----------------
__global__ __launch_bounds__(256) void gather_kernel(const float* __restrict__ x) {
    __shared__ int    s_pos[NFULL];          // 16 KB
    __shared__ __half s_stage[4 * KACT];     // 8 KB
    const int tid = threadIdx.x;
    for (int i = tid; i < NFULL; i += 256) s_pos[i] = g_pos[i];
    __syncthreads();

    const size_t r0 = (size_t)blockIdx.x * 4;
    const float4* __restrict__ x4 = (const float4*)x;
    #pragma unroll
    for (int i = 0; i < 16; i++) {
        int f = tid + i * 256;
        int rowl = f >> 10;
        int c4 = f & 1023;
        float4 v = x4[(r0 + rowl) * (NFULL / 4) + c4];
        int c = c4 * 4;
        float vv[4] = {v.x, v.y, v.z, v.w};
        #pragma unroll
        for (int j = 0; j < 4; j++) {
            int p = s_pos[c + j];
            if (p >= 0) s_stage[rowl * KACT + p] = __float2half_rn(vv[j]);
        }
    }
    __syncthreads();

    // write 4 rows x 1024 fp16 = 512 uint4, fully coalesced
    uint4* __restrict__ dst = (uint4*)(g_xa + r0 * KACT);
    const uint4* __restrict__ src = (const uint4*)s_stage;
    dst[tid]       = src[tid];
    dst[tid + 256] = src[tid + 256];
}

// ---------------- kernel 3: W*2048 -> fp16 ----------------
__global__ __launch_bounds__(256) void conv_w_kernel(const float* __restrict__ W) {
    int i = blockIdx.x * blockDim.x + threadIdx.x;      // float4 index
    float4 v = ((const float4*)W)[i];
    uint2 hp;
    hp.x = pack_h2(v.x * WSCALE, v.y * WSCALE);
    hp.y = pack_h2(v.z * WSCALE, v.w * WSCALE);
    ((uint2*)g_wf)[i] = hp;
}

// ---------------- kernel 4: fp16 mma GEMM + fused zero-fill/bias/scatter ----------------
extern __shared__ char dynsmem[];

__global__ __launch_bounds__(NTHREADS, 3)
void nsl_mma_gemm(const float* __restrict__ bias, const int* __restrict__ out_idx,
                  float* __restrict__ out) {
    __shared__ float s_bias[BN];

    const int tid  = threadIdx.x;
    const int wid  = tid >> 5;
    const int lane = tid & 31;
    const int wm   = wid & 3;         // 0..3 : 32-row band
    const int wn   = wid >> 2;        // 0..1 : 32-col band
    const int m0   = blockIdx.y * BM;
    const int n0   = blockIdx.x * BN; // local col block in [0, 1024)

    if (tid < BN) s_bias[tid] = __ldg(bias + n0 + tid);

    const uint32_t sbase = (smem_u32(dynsmem) + 127) & ~127u;

    // per-thread load assignment: 128B rows, 8 segs/row
    // A: 128 rows x 8 segs = 1024 -> 4/thread; B: 64 rows x 8 segs = 512 -> 2/thread
    const int r = tid >> 3, p = tid & 7;        // r 0..31, p 0..7
    const __half* __restrict__ srcA = g_xa + (size_t)m0 * KACT + (size_t)r * KACT + p * 8;
    const __half* __restrict__ srcB = g_wf + (size_t)n0 * KACT + (size_t)r * KACT + p * 8;
    uint32_t dswA[4], dswB[2];
    #pragma unroll
    for (int i = 0; i < 4; i++) dswA[i] = swz(r + i * 32, p);
    #pragma unroll
    for (int i = 0; i < 2; i++) dswB[i] = A_PLANE + swz(r + i * 32, p);

    auto load_stage = [&](int stage, int kc) {
        const uint32_t sb = sbase + stage * STAGE_BYTES;
        const int ko = kc * BKB;
        #pragma unroll
        for (int i = 0; i < 4; i++)
            cp_async16(sb + dswA[i], srcA + (size_t)(i * 32) * KACT + ko);
        #pragma unroll
        for (int i = 0; i < 2; i++)
            cp_async16(sb + dswB[i], srcB + (size_t)(i * 32) * KACT + ko);
        asm volatile("cp.async.commit_group;");
    };

    // ldmatrix per-lane state
    const int lrow = lane & 15;
    const int hi   = lane >> 4;                 // 16B half within k16 step
    const int rot  = lrow & 7;                  // XOR rotation (row & 7)
    uint32_t aRow[2], bRow[2];
    #pragma unroll
    for (int f = 0; f < 2; f++)
        aRow[f] = (uint32_t)((wm * 32 + f * 16 + lrow) * 128);
    #pragma unroll
    for (int q = 0; q < 2; q++)
        bRow[q] = (uint32_t)(A_PLANE + (wn * 32 + q * 16 + lrow) * 128);

    float acc[2][4][4];
    #pragma unroll
    for (int i = 0; i < 2; i++)
        #pragma unroll
        for (int j = 0; j < 4; j++)
            #pragma unroll
            for (int q = 0; q < 4; q++) acc[i][j][q] = 0.f;

    load_stage(0, 0);
    load_stage(1, 1);

    for (int t = 0; t < NITER; t++) {
        if (t < NITER - 1) asm volatile("cp.async.wait_group 1;" ::: "memory");
        else               asm volatile("cp.async.wait_group 0;" ::: "memory");
        __syncthreads();
        if (t + 2 < NITER) load_stage((t + 2) % STAGES, t + 2);

        const uint32_t sb = sbase + (t % STAGES) * STAGE_BYTES;
        #pragma unroll
        for (int kk = 0; kk < 4; kk++) {            // 4 x k16 steps
            const uint32_t co = (uint32_t)((((kk * 2 + hi) ^ rot) & 7) << 4);
            uint32_t a[2][4], bf[2][4];
            ldsm4(a[0],  sb + aRow[0] + co);
            ldsm4(a[1],  sb + aRow[1] + co);
            ldsm4(bf[0], sb + bRow[0] + co);
            ldsm4(bf[1], sb + bRow[1] + co);

            #pragma unroll
            for (int mi = 0; mi < 2; mi++)
                #pragma unroll
                for (int q = 0; q < 2; q++) {
                    mma_f16(acc[mi][2 * q + 0], a[mi], bf[q][0], bf[q][2]);
                    mma_f16(acc[mi][2 * q + 1], a[mi], bf[q][1], bf[q][3]);
                }
        }
    }

    // ---- epilogue: stage tile to smem, then ranged full-width write ----
    __syncthreads();                         // all LDSM reads of pipeline smem done
    float* stile = (float*)dynsmem;          // reuse pipeline smem: 128x64 fp32 = 32 KB

    const int rq = lane >> 2, cq = (lane & 3) * 2;
    #pragma unroll
    for (int mi = 0; mi < 2; mi++) {
        const int rb = wm * 32 + mi * 16 + rq;
        #pragma unroll
        for (int nf = 0; nf < 4; nf++) {
            const int nl = wn * 32 + nf * 8 + cq;
            const float* c = acc[mi][nf];
            stile[rb * BN + nl]           = c[0];
            stile[rb * BN + nl + 1]       = c[1];
            stile[(rb + 8) * BN + nl]     = c[2];
            stile[(rb + 8) * BN + nl + 1] = c[3];
        }
    }
    __syncthreads();

    // owned output-column range (out_idx sorted): [sBeg, sEnd)
    const int j = blockIdx.x;
    const int sBeg = (j == 0)             ? 0     : __ldg(out_idx + n0);
    const int sEnd = (j == NACT / BN - 1) ? NFULL : __ldg(out_idx + n0 + BN);

    for (int c = sBeg + tid; c < sEnd; c += NTHREADS) {
        const int pp  = __ldg(g_opos + c);           // >=0 iff active; then in [n0,n0+64)
        const bool act = (pp >= 0);
        const int nl  = act ? (pp - n0) : 0;
        const float bv = act ? s_bias[nl] : 0.f;
        float* __restrict__ ocol = out + (size_t)m0 * NFULL + c;
        #pragma unroll 8
        for (int m = 0; m < BM; m++) {
            float v = act ? fmaf(stile[m * BN + nl], INV_WSCALE, bv) : 0.f;
            ocol[(size_t)m * NFULL] = v;
        }
    }
}

// ---------------- launch ----------------
extern "C" void kernel_launch(void* const* d_in, const int* in_sizes, int n_in,
                              void* d_out, int out_size) {
    const float* x       = (const float*)d_in[0];
    const float* W       = (const float*)d_in[1];
    const float* b       = (const float*)d_in[2];
    const int*   in_idx  = (const int*)d_in[3];
    const int*   out_idx = (const int*)d_in[4];
    float*       out     = (float*)d_out;

    static bool attr_set = false;
    if (!attr_set) {
        cudaFuncSetAttribute(nsl_mma_gemm, cudaFuncAttributeMaxDynamicSharedMemorySize,
                             SMEM_BYTES);
        attr_set = true;
    }

    build_maps_kernel<<<(NFULL + 255) / 256, 256>>>(in_idx, out_idx);
    conv_w_kernel<<<(NACT * KACT / 4) / 256, 256>>>(W);
    gather_kernel<<<MROWS / 4, 256>>>(x);

    dim3 grid(NACT / BN, MROWS / BM);   // (16, 64) = 1024 CTAs
    nsl_mma_gemm<<<grid, NTHREADS, SMEM_BYTES>>>(b, out_idx, out);
}